// round 15
// baseline (speedup 1.0000x reference)
#include <cuda_runtime.h>
#include <cstdint>

#define BATCH 128
#define NNODE 2048
#define ND 128      // NODE_DIM
#define QD 256      // QUERY_DIM
#define OD 256      // OUT_DIM
#define SLICES 2
#define SLICE_NODES (NNODE/SLICES)          // 1024
#define K1_WARPS 8
#define K1_THREADS 256
#define NODES_PER_WARP (SLICE_NODES/K1_WARPS)  // 128
#define BT 8                                 // nodes per register batch
#define NB (NODES_PER_WARP/BT)               // 16 batches
#define PSTRIDE 272                          // floats per partial record

__device__ __align__(16) float g_part[BATCH*SLICES*PSTRIDE];
__device__ int g_ticket[BATCH];              // zero-init; reset by epilogue CTA

#define COMPUTE(X, ii) { \
    float p1[BT], p2[BT]; \
    _Pragma("unroll") for (int j = 0; j < BT; j++) { \
        p1[j] = X[j].x*q1r.x + X[j].y*q1r.y + X[j].z*q1r.z + X[j].w*q1r.w; \
        p2[j] = X[j].x*q2r.x + X[j].y*q2r.y + X[j].z*q2r.z + X[j].w*q2r.w; } \
    _Pragma("unroll") for (int o = 16; o > 0; o >>= 1) { \
        _Pragma("unroll") for (int j = 0; j < BT; j++) { \
            p1[j] += __shfl_xor_sync(0xffffffffu, p1[j], o); \
            p2[j] += __shfl_xor_sync(0xffffffffu, p2[j], o); } } \
    _Pragma("unroll") for (int j = 0; j < BT; j++) { \
        float pd = pads[pbase + (ii)*BT + j]; \
        float e1 = __expf(p1[j] + pd); \
        float e2 = __expf(p2[j] + pd); \
        L1 += e1; L2 += e2; \
        c1.x += e1*X[j].x; c1.y += e1*X[j].y; c1.z += e1*X[j].z; c1.w += e1*X[j].w; \
        c2.x += e2*X[j].x; c2.y += e2*X[j].y; c2.z += e2*X[j].z; c2.w += e2*X[j].w; } }

__global__ __launch_bounds__(K1_THREADS, 2)
void gar_fused(const float* __restrict__ node_mat,
               const void*  __restrict__ mask,
               const float* __restrict__ fp_vec,
               const float* __restrict__ Wq1,
               const float* __restrict__ Wq2,
               const float* __restrict__ Wk,
               const float* __restrict__ Wv,
               const float* __restrict__ lambda_logit,
               const float* __restrict__ gamma,
               const float* __restrict__ beta,
               float* __restrict__ out)
{
    __shared__ float pads[SLICE_NODES];                                    // 4 KB
    __shared__ __align__(16) float wacc1[K1_WARPS*ND], wacc2[K1_WARPS*ND]; // 8 KB
    __shared__ __align__(16) float qs[2*ND];                               // 1 KB
    __shared__ __align__(16) float q1t[ND], q2t[ND];                       // 1 KB
    __shared__ __align__(16) float ztd[ND];
    __shared__ float wl1[K1_WARPS], wl2[K1_WARPS];
    __shared__ float red[8];
    __shared__ int smode, sticket;

    const int t = threadIdx.x;
    const int bid = blockIdx.x;
    const int b = bid >> 1, q = bid & 1;
    const int w = t >> 5, l = t & 31;

    // this warp's contiguous 128-node region
    const float4* p = (const float4*)node_mat
        + ((size_t)b*NNODE + q*SLICE_NODES + w*NODES_PER_WARP) * (ND/4) + l;
    const int pbase = w*NODES_PER_WARP;

    // ---- prefetch batch 0 FIRST (no dependency on queries) ----
    float4 A[BT], Bf[BT];
    #pragma unroll
    for (int j = 0; j < BT; j++) A[j] = p[j*32];

    // ---- mask dtype sniff ----
    if (t == 0) smode = 0;
    __syncthreads();
    {
        const unsigned* mw = (const unsigned*)mask;
        #pragma unroll
        for (int r = 0; r < 2; r++) {
            unsigned v = mw[b*512 + t + r*256];
            int f = 0;
            if (v == 0x3F800000u)        f = 2;   // fp32 one
            else if (v != 0u && v != 1u) f = 1;   // byte-packed bool signature
            if (f) atomicOr(&smode, f);
        }
    }
    __syncthreads();
    {
        const int mode = smode;
        const size_t off = (size_t)b*NNODE + q*SLICE_NODES;
        const int*           mi  = (const int*)mask           + off;
        const unsigned char* mu8 = (const unsigned char*)mask + off;
        const float*         mf  = (const float*)mask         + off;
        #pragma unroll
        for (int r = 0; r < SLICE_NODES/K1_THREADS; r++) {
            int n = t + r*K1_THREADS;
            bool valid;
            if (mode & 1)      valid = mu8[n] != 0;
            else if (mode & 2) valid = mf[n]  != 0.f;
            else               valid = mi[n]  != 0;
            pads[n] = valid ? 0.f : -1e9f;
        }
    }

    // ---- in-kernel query precompute (redundant per slice CTA) ----
    // phase 1: qs[o] = fp[b]·Wq{1,2}[o,:]  (warp w owns outputs w*32..w*32+31)
    {
        const float4* fp4 = (const float4*)(fp_vec + b*QD);
        const float4 fa = fp4[l], fb = fp4[l + 32];
        #pragma unroll
        for (int k = 0; k < 32; k += 4) {
            float pp[4];
            #pragma unroll
            for (int j = 0; j < 4; j++) {
                const int o = w*32 + k + j;
                const float* rowp = (o < ND) ? (Wq1 + o*QD) : (Wq2 + (o-ND)*QD);
                const float4* r4 = (const float4*)rowp;
                float4 ra = r4[l], rb = r4[l + 32];
                pp[j] = fa.x*ra.x + fa.y*ra.y + fa.z*ra.z + fa.w*ra.w
                      + fb.x*rb.x + fb.y*rb.y + fb.z*rb.z + fb.w*rb.w;
            }
            #pragma unroll
            for (int o2 = 16; o2 > 0; o2 >>= 1) {
                pp[0] += __shfl_xor_sync(0xffffffffu, pp[0], o2);
                pp[1] += __shfl_xor_sync(0xffffffffu, pp[1], o2);
                pp[2] += __shfl_xor_sync(0xffffffffu, pp[2], o2);
                pp[3] += __shfl_xor_sync(0xffffffffu, pp[3], o2);
            }
            if (l < 4) {
                float v = (l==0) ? pp[0] : (l==1) ? pp[1] : (l==2) ? pp[2] : pp[3];
                qs[w*32 + k + l] = v;
            }
        }
    }
    __syncthreads();
    // phase 2: q{1,2}t[d] = inv_scale * sum_e qs[..]*Wk[e,d]   (coalesced over d)
    {
        const int d  = t & (ND-1);
        const int br = t >> 7;
        const float* qv = qs + br*ND;
        float s0 = 0.f, s1 = 0.f, s2 = 0.f, s3 = 0.f;
        #pragma unroll
        for (int e = 0; e < ND; e += 4) {
            s0 += qv[e+0] * Wk[(e+0)*ND + d];
            s1 += qv[e+1] * Wk[(e+1)*ND + d];
            s2 += qv[e+2] * Wk[(e+2)*ND + d];
            s3 += qv[e+3] * Wk[(e+3)*ND + d];
        }
        float s = ((s0+s1) + (s2+s3)) * 0.08838834764831845f;  // 1/sqrt(128)
        if (br == 0) q1t[d] = s; else q2t[d] = s;
    }
    __syncthreads();

    const float4 q1r = ((const float4*)q1t)[l];   // lane owns dims [4l,4l+4)
    const float4 q2r = ((const float4*)q2t)[l];

    float4 c1 = make_float4(0.f,0.f,0.f,0.f), c2 = c1;
    float L1 = 0.f, L2 = 0.f;

    // ---- streaming loop: depth-2 software pipeline of 8-node batches ----
    for (int i = 0; i < NB; i += 2) {
        #pragma unroll
        for (int j = 0; j < BT; j++) Bf[j] = p[((i+1)*BT + j)*32];
        COMPUTE(A, i)
        if (i + 2 < NB) {
            #pragma unroll
            for (int j = 0; j < BT; j++) A[j] = p[((i+2)*BT + j)*32];
        }
        COMPUTE(Bf, i+1)
    }

    // ---- publish per-warp partials ----
    ((float4*)(wacc1 + w*ND))[l] = c1;
    ((float4*)(wacc2 + w*ND))[l] = c2;
    if (l == 0) { wl1[w] = L1; wl2[w] = L2; }
    __syncthreads();

    if (t < ND) {
        float z1 = 0.f, z2 = 0.f;
        #pragma unroll
        for (int k = 0; k < K1_WARPS; k++) { z1 += wacc1[k*ND + t]; z2 += wacc2[k*ND + t]; }
        float* P = g_part + (size_t)bid*PSTRIDE;
        P[t] = z1; P[ND + t] = z2;
    }
    if (t == 0) {
        float tL1 = 0.f, tL2 = 0.f;
        #pragma unroll
        for (int k = 0; k < K1_WARPS; k++) { tL1 += wl1[k]; tL2 += wl2[k]; }
        float* P = g_part + (size_t)bid*PSTRIDE;
        P[2*ND] = tL1; P[2*ND+1] = tL2;
    }
    __syncthreads();

    // ---- last-CTA-of-pair ticket: second CTA does the epilogue ----
    if (t == 0) {
        __threadfence();
        sticket = atomicAdd(&g_ticket[b], 1);
    }
    __syncthreads();
    if (sticket != 1) return;      // first finisher exits

    // ---- epilogue (merge + Wv + LayerNorm) on this CTA ----
    const float* P0 = g_part + (size_t)(b*2)   * PSTRIDE;
    const float* P1 = g_part + (size_t)(b*2+1) * PSTRIDE;
    if (t < ND) {
        float z1 = P0[t]      + P1[t];
        float z2 = P0[ND+t]   + P1[ND+t];
        float tL1 = P0[2*ND]   + P1[2*ND];
        float tL2 = P0[2*ND+1] + P1[2*ND+1];
        float lam = 0.8f + 0.2f / (1.f + __expf(-lambda_logit[0]));
        ztd[t] = z1/tL1 - lam*(z2/tL2);
    }
    if (t == 0) g_ticket[b] = 0;   // reset for next graph replay
    __syncthreads();

    float zv = 0.f;
    {
        const float4* wr = (const float4*)(Wv + t*ND);
        const float4* z4 = (const float4*)ztd;
        #pragma unroll 8
        for (int d4 = 0; d4 < ND/4; d4++) {
            float4 a = z4[d4], ww = wr[d4];
            zv += a.x*ww.x + a.y*ww.y + a.z*ww.z + a.w*ww.w;
        }
    }
    float s = zv;
    #pragma unroll
    for (int o = 16; o > 0; o >>= 1) s += __shfl_xor_sync(0xffffffffu, s, o);
    if (l == 0) red[w] = s;
    __syncthreads();
    float tot = 0.f;
    #pragma unroll
    for (int k = 0; k < 8; k++) tot += red[k];
    float mu = tot / OD;

    float dv = zv - mu;
    float sq = dv*dv;
    __syncthreads();   // red reuse
    #pragma unroll
    for (int o = 16; o > 0; o >>= 1) sq += __shfl_xor_sync(0xffffffffu, sq, o);
    if (l == 0) red[w] = sq;
    __syncthreads();
    float tot2 = 0.f;
    #pragma unroll
    for (int k = 0; k < 8; k++) tot2 += red[k];
    float inv = rsqrtf(tot2 / OD + 1e-5f);

    out[b*OD + t] = dv*inv*gamma[t] + beta[t];
}

extern "C" void kernel_launch(void* const* d_in, const int* in_sizes, int n_in,
                              void* d_out, int out_size) {
    gar_fused<<<BATCH*SLICES, K1_THREADS>>>(
        (const float*)d_in[1],   // node_mat
        d_in[2],                 // mask
        (const float*)d_in[0],   // fp_vec
        (const float*)d_in[3],   // Wq1
        (const float*)d_in[4],   // Wq2
        (const float*)d_in[5],   // Wk
        (const float*)d_in[6],   // Wv
        (const float*)d_in[7],   // lambda_logit
        (const float*)d_in[8],   // gamma
        (const float*)d_in[9],   // beta
        (float*)d_out);
}